// round 11
// baseline (speedup 1.0000x reference)
#include <cuda_runtime.h>
#include <cuda_fp16.h>
#include <mma.h>
#include <cstdint>

using namespace nvcuda;

#define BB    2
#define NTOK  2048
#define DIM   128
#define NH    8
#define DOUT  256
#define BN_   (BB*NTOK)            // 4096
#define FEAT  (NH*DIM)             // 1024
#define SC2E  0.03187935797f       // (1/sqrt(2048)) * log2(e)
#define LDH   136                  // fp16 tile leading dim (272 B rows)
#define LDS4  132                  // fp32 staging leading dim (qkv kernel)
#define TB    34816                // one 128 x LDH fp16 tile buffer
#define LDW   264                  // Wout smem leading dim (528 B rows)

#define ADJ_GRID  4096             // 8.39M float4 / (256 threads * 8 per thread)
#define BIAS_GRID 1024             // 262144 float4 / 256

// ---- scratch (sanctioned __device__ globals) ----
__device__ __align__(16) __half g_adjsumh[(size_t)BB*NTOK*NTOK];    // 16.8 MB
__device__ __align__(16) __half g_q[(size_t)NH*BN_*DIM];            // 8.4 MB
__device__ __align__(16) __half g_k[(size_t)NH*BN_*DIM];
__device__ __align__(16) __half g_v[(size_t)NH*BN_*DIM];

// ---- PTX helpers ----
__device__ __forceinline__ void cp16(uint32_t saddr, const void* gptr) {
    asm volatile("cp.async.cg.shared.global [%0], [%1], 16;"
                 :: "r"(saddr), "l"(gptr));
}
#define CP_COMMIT() asm volatile("cp.async.commit_group;" ::: "memory")
#define CP_WAIT1()  asm volatile("cp.async.wait_group 1;" ::: "memory")
#define CP_WAIT0()  asm volatile("cp.async.wait_group 0;" ::: "memory")

__device__ __forceinline__ void ldsm_x4(uint32_t& r0, uint32_t& r1,
                                        uint32_t& r2, uint32_t& r3, uint32_t a) {
    asm volatile("ldmatrix.sync.aligned.m8n8.x4.shared.b16 {%0,%1,%2,%3}, [%4];"
                 : "=r"(r0), "=r"(r1), "=r"(r2), "=r"(r3) : "r"(a));
}
__device__ __forceinline__ void ldsm_x4t(uint32_t& r0, uint32_t& r1,
                                         uint32_t& r2, uint32_t& r3, uint32_t a) {
    asm volatile("ldmatrix.sync.aligned.m8n8.x4.trans.shared.b16 {%0,%1,%2,%3}, [%4];"
                 : "=r"(r0), "=r"(r1), "=r"(r2), "=r"(r3) : "r"(a));
}
__device__ __forceinline__ void mma16816(float* c, const uint32_t* a,
                                         uint32_t b0, uint32_t b1) {
    asm volatile("mma.sync.aligned.m16n8k16.row.col.f32.f16.f16.f32 "
                 "{%0,%1,%2,%3}, {%4,%5,%6,%7}, {%8,%9}, {%0,%1,%2,%3};"
                 : "+f"(c[0]), "+f"(c[1]), "+f"(c[2]), "+f"(c[3])
                 : "r"(a[0]), "r"(a[1]), "r"(a[2]), "r"(a[3]), "r"(b0), "r"(b1));
}
__device__ __forceinline__ float ex2f(float x) {
    float y;
    asm("ex2.approx.ftz.f32 %0, %1;" : "=f"(y) : "f"(x));
    return y;
}

// ============================================================
// K1: blocks [0, ADJ_GRID): adjsumh = fp16(sum_w adj), 8 float4/thread
//     (MLP=8 batched loads, one 16B store);
//     blocks [ADJ_GRID, +BIAS_GRID): out = bias broadcast (pre-init for atomics)
// ============================================================
__global__ void adjsum_kernel(const float4* __restrict__ adj,
                              const float4* __restrict__ bout4,
                              float4* __restrict__ out4) {
    const int tid = threadIdx.x;
    if (blockIdx.x < ADJ_GRID) {
        const size_t base = ((size_t)blockIdx.x * 256 + tid) * 8;
        float4 t[8];
        #pragma unroll
        for (int j = 0; j < 8; j++) t[j] = adj[base + j];
        __half h[8];
        #pragma unroll
        for (int j = 0; j < 8; j++)
            h[j] = __float2half_rn((t[j].x + t[j].y) + (t[j].z + t[j].w));
        *(uint4*)&g_adjsumh[base] = *(const uint4*)h;
    } else {
        size_t j = (size_t)(blockIdx.x - ADJ_GRID) * 256 + tid;
        out4[j] = bout4[j & 63];
    }
}

// ============================================================
// K2: q/k/v[h] = fp16( X @ W[h] + b[h] )   (unchanged, proven)
// ============================================================
__global__ void qkv_kernel(const float* __restrict__ X,
                           const float* __restrict__ Wq, const float* __restrict__ bq,
                           const float* __restrict__ Wk, const float* __restrict__ bk,
                           const float* __restrict__ Wv, const float* __restrict__ bv) {
    __shared__ __align__(16) char smem_raw[17408 + TB];
    __half* sA = (__half*)smem_raw;
    __half* sB = (__half*)(smem_raw + 17408);
    float*  sO = (float*)(smem_raw + 17408);
    const int tid  = threadIdx.x;
    const int warp = tid >> 5;
    const int wr = warp >> 2, wc = warp & 3;
    const int row0 = blockIdx.x * 64;
    const int z = blockIdx.y;
    const int mat = z >> 3, h = z & 7;

    const float* Wm = (mat == 0 ? Wq : (mat == 1 ? Wk : Wv)) + (size_t)h*DIM*DIM;
    const float* bm = (mat == 0 ? bq : (mat == 1 ? bk : bv)) + (size_t)h*DIM;
    __half* outp = (mat == 0 ? g_q : (mat == 1 ? g_k : g_v)) + (size_t)h*BN_*DIM;

    for (int idx = tid; idx < 64*32; idx += 256) {
        int r = idx >> 5, c = idx & 31;
        float4 t = *(const float4*)(X + (size_t)(row0 + r)*DIM + c*4);
        __half2* d = (__half2*)(sA + r*LDH + c*4);
        d[0] = __floats2half2_rn(t.x, t.y);
        d[1] = __floats2half2_rn(t.z, t.w);
    }
    for (int idx = tid; idx < 128*32; idx += 256) {
        int r = idx >> 5, c = idx & 31;
        float4 t = *(const float4*)(Wm + (size_t)r*DIM + c*4);
        __half2* d = (__half2*)(sB + r*LDH + c*4);
        d[0] = __floats2half2_rn(t.x, t.y);
        d[1] = __floats2half2_rn(t.z, t.w);
    }
    __syncthreads();

    wmma::fragment<wmma::accumulator,16,16,16,float> acc[2][2];
    #pragma unroll
    for (int i = 0; i < 2; i++)
        #pragma unroll
        for (int j = 0; j < 2; j++) wmma::fill_fragment(acc[i][j], 0.0f);

    #pragma unroll
    for (int k = 0; k < 8; k++) {
        wmma::fragment<wmma::matrix_a,16,16,16,__half,wmma::row_major> fa[2];
        wmma::fragment<wmma::matrix_b,16,16,16,__half,wmma::row_major> fb[2];
        #pragma unroll
        for (int i = 0; i < 2; i++)
            wmma::load_matrix_sync(fa[i], sA + (wr*32 + i*16)*LDH + k*16, LDH);
        #pragma unroll
        for (int j = 0; j < 2; j++)
            wmma::load_matrix_sync(fb[j], sB + (k*16)*LDH + wc*32 + j*16, LDH);
        #pragma unroll
        for (int i = 0; i < 2; i++)
            #pragma unroll
            for (int j = 0; j < 2; j++)
                wmma::mma_sync(acc[i][j], fa[i], fb[j], acc[i][j]);
    }
    __syncthreads();
    #pragma unroll
    for (int i = 0; i < 2; i++)
        #pragma unroll
        for (int j = 0; j < 2; j++)
            wmma::store_matrix_sync(sO + (wr*32 + i*16)*LDS4 + wc*32 + j*16,
                                    acc[i][j], LDS4, wmma::mem_row_major);
    __syncthreads();
    for (int idx = tid; idx < 64*128; idx += 256) {
        int r = idx >> 7, e = idx & 127;
        outp[(size_t)(row0 + r)*DIM + e] = __float2half_rn(sO[r*LDS4 + e] + bm[e]);
    }
}

// ============================================================
// K3 (FUSED FA2 + output projection epilogue — unchanged, proven)
// ============================================================
__global__ __launch_bounds__(256, 1) void fused_attn_fa2(
        const float* __restrict__ Wout, float* __restrict__ out) {
    extern __shared__ __align__(16) char dsm[];
    const uint32_t uBase = (uint32_t)__cvta_generic_to_shared(dsm);

    const int tid  = threadIdx.x;
    const int warp = tid >> 5;
    const int lane = tid & 31;
    const int g    = lane >> 2;
    const int tg   = lane & 3;
    const int n0 = blockIdx.x * 128;
    const int b = blockIdx.y >> 3, h = blockIdx.y & 7;

    const __half* qp  = g_q + (size_t)h*BN_*DIM + (size_t)b*NTOK*DIM;
    const __half* kp  = g_k + (size_t)h*BN_*DIM + (size_t)b*NTOK*DIM;
    const __half* vp  = g_v + (size_t)h*BN_*DIM + (size_t)b*NTOK*DIM;
    const __half* adjp = g_adjsumh + (size_t)b*NTOK*NTOK + (size_t)n0*NTOK;

    const int lrow_a = ((lane >> 3) & 1)*8 + (lane & 7);
    const int lcol_a = (lane >> 4)*8;
    const int lrow_b = ((lane >> 4) & 1)*8 + (lane & 7);
    const int lcol_b = ((lane >> 3) & 1)*8;

    // ---- prologue: stage Q through smem, extract a-frags ----
    for (int idx = tid; idx < 128*16; idx += 256) {
        int r = idx >> 4, c = idx & 15;
        *(uint4*)(dsm + r*272 + c*16) = *(const uint4*)(qp + (size_t)(n0 + r)*DIM + c*8);
    }
    __syncthreads();
    uint32_t aQ[8][4];
    #pragma unroll
    for (int kk = 0; kk < 8; kk++) {
        uint32_t a = uBase + (uint32_t)(warp*16 + lrow_a)*272 + (kk*16 + lcol_a)*2;
        ldsm_x4(aQ[kk][0], aQ[kk][1], aQ[kk][2], aQ[kk][3], a);
    }
    __syncthreads();

    #pragma unroll
    for (int j = 0; j < 2; j++) {
        const uint32_t uK = uBase + j*TB, uV = uBase + (2 + j)*TB, uA = uBase + (4 + j)*TB;
        const int m0 = j*128;
        for (int idx = tid; idx < 128*16; idx += 256) {
            int r = idx >> 4, c = idx & 15;
            cp16(uK + r*272 + c*16, kp + (size_t)(m0 + r)*DIM + c*8);
        }
        for (int idx = tid; idx < 128*16; idx += 256) {
            int r = idx >> 4, c = idx & 15;
            cp16(uV + r*272 + c*16, vp + (size_t)(m0 + r)*DIM + c*8);
        }
        for (int idx = tid; idx < 128*16; idx += 256) {
            int r = idx >> 4, c = idx & 15;
            cp16(uA + r*272 + c*16, adjp + (size_t)r*NTOK + m0 + c*8);
        }
        CP_COMMIT();
    }

    float oacc[16][4];
    #pragma unroll
    for (int j = 0; j < 16; j++)
        #pragma unroll
        for (int e = 0; e < 4; e++) oacc[j][e] = 0.f;
    float lsum0 = 0.f, lsum1 = 0.f;

    for (int it = 0; it < 16; it++) {
        const int bi = it & 1;
        const uint32_t uK = uBase + bi*TB;
        const uint32_t uV = uBase + (2 + bi)*TB;
        const __half* sAdj = (const __half*)(dsm + (size_t)(4 + bi)*TB);

        if (it < 15) { CP_WAIT1(); } else { CP_WAIT0(); }
        __syncthreads();

        // ---- S = Q K^T ----
        float sacc[16][4];
        #pragma unroll
        for (int j = 0; j < 16; j++)
            #pragma unroll
            for (int e = 0; e < 4; e++) sacc[j][e] = 0.f;
        #pragma unroll
        for (int kk = 0; kk < 8; kk++) {
            #pragma unroll
            for (int jjp = 0; jjp < 8; jjp++) {
                uint32_t r0, r1, r2, r3;
                ldsm_x4(r0, r1, r2, r3,
                        uK + (uint32_t)(jjp*16 + lrow_b)*272 + (kk*16 + lcol_b)*2);
                mma16816(sacc[2*jjp],     aQ[kk], r0, r1);
                mma16816(sacc[2*jjp + 1], aQ[kk], r2, r3);
            }
        }

        // ---- exp in registers (ex2 with folded scale) ----
        uint32_t aP[8][4];
        const int row0 = warp*16 + g;
        #pragma unroll
        for (int jj = 0; jj < 16; jj++) {
            const int col = jj*8 + tg*2;
            float2 a0 = __half22float2(*(const __half2*)(sAdj + row0*LDH + col));
            float2 a1 = __half22float2(*(const __half2*)(sAdj + (row0 + 8)*LDH + col));
            float e00 = ex2f(sacc[jj][0] * SC2E * a0.x);
            float e01 = ex2f(sacc[jj][1] * SC2E * a0.y);
            float e10 = ex2f(sacc[jj][2] * SC2E * a1.x);
            float e11 = ex2f(sacc[jj][3] * SC2E * a1.y);
            lsum0 += e00 + e01;
            lsum1 += e10 + e11;
            __half2 p0 = __floats2half2_rn(e00, e01);
            __half2 p1 = __floats2half2_rn(e10, e11);
            aP[jj >> 1][(jj & 1)*2 + 0] = *(uint32_t*)&p0;
            aP[jj >> 1][(jj & 1)*2 + 1] = *(uint32_t*)&p1;
        }

        // ---- O += P @ V ----
        #pragma unroll
        for (int kk = 0; kk < 8; kk++) {
            #pragma unroll
            for (int jop = 0; jop < 8; jop++) {
                uint32_t r0, r1, r2, r3;
                ldsm_x4t(r0, r1, r2, r3,
                         uV + (uint32_t)(kk*16 + lrow_a)*272 + (jop*16 + lcol_a)*2);
                mma16816(oacc[2*jop],     aP[kk], r0, r1);
                mma16816(oacc[2*jop + 1], aP[kk], r2, r3);
            }
        }
        __syncthreads();

        if (it + 2 < 16) {
            const int m2 = (it + 2)*128;
            for (int idx = tid; idx < 128*16; idx += 256) {
                int r = idx >> 4, c = idx & 15;
                cp16(uK + r*272 + c*16, kp + (size_t)(m2 + r)*DIM + c*8);
            }
            for (int idx = tid; idx < 128*16; idx += 256) {
                int r = idx >> 4, c = idx & 15;
                cp16(uV + r*272 + c*16, vp + (size_t)(m2 + r)*DIM + c*8);
            }
            const uint32_t uA = uBase + (4 + bi)*TB;
            for (int idx = tid; idx < 128*16; idx += 256) {
                int r = idx >> 4, c = idx & 15;
                cp16(uA + r*272 + c*16, adjp + (size_t)r*NTOK + m2 + c*8);
            }
            CP_COMMIT();
        }
    }

    // ---- epilogue 1: row sums -> normalized O as A-frags (c->a identity) ----
    lsum0 += __shfl_xor_sync(0xFFFFFFFF, lsum0, 1);
    lsum0 += __shfl_xor_sync(0xFFFFFFFF, lsum0, 2);
    lsum1 += __shfl_xor_sync(0xFFFFFFFF, lsum1, 1);
    lsum1 += __shfl_xor_sync(0xFFFFFFFF, lsum1, 2);
    const float inv0 = 1.0f / lsum0;
    const float inv1 = 1.0f / lsum1;
    uint32_t aO[8][4];
    #pragma unroll
    for (int kk = 0; kk < 8; kk++) {
        __half2 p;
        p = __floats2half2_rn(oacc[2*kk][0]*inv0,   oacc[2*kk][1]*inv0);
        aO[kk][0] = *(uint32_t*)&p;
        p = __floats2half2_rn(oacc[2*kk][2]*inv1,   oacc[2*kk][3]*inv1);
        aO[kk][1] = *(uint32_t*)&p;
        p = __floats2half2_rn(oacc[2*kk+1][0]*inv0, oacc[2*kk+1][1]*inv0);
        aO[kk][2] = *(uint32_t*)&p;
        p = __floats2half2_rn(oacc[2*kk+1][2]*inv1, oacc[2*kk+1][3]*inv1);
        aO[kk][3] = *(uint32_t*)&p;
    }

    // ---- epilogue 2: stage Wout slice [h*128 .. +128) x 256 as fp16 ----
    const float* wsl = Wout + (size_t)(h*DIM)*DOUT;
    for (int idx = tid; idx < 128*64; idx += 256) {
        int r = idx >> 6, c4 = idx & 63;
        float4 t = *(const float4*)(wsl + (size_t)r*DOUT + c4*4);
        __half2* d = (__half2*)((__half*)dsm + r*LDW + c4*4);
        d[0] = __floats2half2_rn(t.x, t.y);
        d[1] = __floats2half2_rn(t.z, t.w);
    }
    __syncthreads();

    // ---- epilogue 3: out_tile(16x256) = O_norm(16x128) @ Wout_slice ----
    float outacc[32][4];
    #pragma unroll
    for (int j = 0; j < 32; j++)
        #pragma unroll
        for (int e = 0; e < 4; e++) outacc[j][e] = 0.f;
    #pragma unroll
    for (int kk = 0; kk < 8; kk++) {
        #pragma unroll
        for (int jop = 0; jop < 16; jop++) {
            uint32_t r0, r1, r2, r3;
            ldsm_x4t(r0, r1, r2, r3,
                     uBase + (uint32_t)(kk*16 + lrow_a)*(LDW*2) + (jop*16 + lcol_a)*2);
            mma16816(outacc[2*jop],     aO[kk], r0, r1);
            mma16816(outacc[2*jop + 1], aO[kk], r2, r3);
        }
    }

    // ---- epilogue 4: atomicAdd into pre-biased out ----
    const int orow = b*NTOK + n0 + warp*16 + g;
    float* o0 = out + (size_t)orow*DOUT;
    float* o1 = o0 + 8*DOUT;
    #pragma unroll
    for (int jt = 0; jt < 32; jt++) {
        const int col = jt*8 + tg*2;
        atomicAdd(o0 + col,     outacc[jt][0]);
        atomicAdd(o0 + col + 1, outacc[jt][1]);
        atomicAdd(o1 + col,     outacc[jt][2]);
        atomicAdd(o1 + col + 1, outacc[jt][3]);
    }
}

// ============================================================
extern "C" void kernel_launch(void* const* d_in, const int* in_sizes, int n_in,
                              void* d_out, int out_size) {
    const float* X    = (const float*)d_in[0];
    const float* adj  = (const float*)d_in[1];
    const float* Wq   = (const float*)d_in[2];
    const float* bq   = (const float*)d_in[3];
    const float* Wk   = (const float*)d_in[4];
    const float* bk   = (const float*)d_in[5];
    const float* Wv   = (const float*)d_in[6];
    const float* bv   = (const float*)d_in[7];
    const float* Wout = (const float*)d_in[8];
    const float* bout = (const float*)d_in[9];
    float* out = (float*)d_out;

    const int fused_smem = 6*TB;   // 208,896 B (epilogue reuse: 67,584 B for Wout)
    cudaFuncSetAttribute(fused_attn_fa2,
                         cudaFuncAttributeMaxDynamicSharedMemorySize, fused_smem);

    adjsum_kernel<<<ADJ_GRID + BIAS_GRID, 256>>>((const float4*)adj,
                                                 (const float4*)bout, (float4*)out);
    qkv_kernel<<<dim3(BN_/64, 3*NH), 256>>>(X, Wq, bq, Wk, bk, Wv, bv);
    fused_attn_fa2<<<dim3(NTOK/128, BB*NH), 256, fused_smem>>>(Wout, out);
}

// round 12
// speedup vs baseline: 1.0271x; 1.0271x over previous
#include <cuda_runtime.h>
#include <cuda_fp16.h>
#include <mma.h>
#include <cstdint>

using namespace nvcuda;

#define BB    2
#define NTOK  2048
#define DIM   128
#define NH    8
#define DOUT  256
#define BN_   (BB*NTOK)            // 4096
#define FEAT  (NH*DIM)             // 1024
#define SC2E  0.03187935797f       // (1/sqrt(2048)) * log2(e)
#define LDH   136                  // fp16 tile leading dim (272 B rows)
#define LDS4  132                  // fp32 staging leading dim (qkv kernel)
#define TB    34816                // one 128 x LDH fp16 tile buffer
#define LDW   264                  // Wout smem leading dim (528 B rows)

#define ADJ_GRID  4096             // 8.39M float4 / (256 threads * 8 strided)
#define BIAS_GRID 1024             // 262144 float4 / 256

// ---- scratch (sanctioned __device__ globals) ----
__device__ __align__(16) __half g_adjsumh[(size_t)BB*NTOK*NTOK];    // 16.8 MB
__device__ __align__(16) __half g_q[(size_t)NH*BN_*DIM];            // 8.4 MB
__device__ __align__(16) __half g_k[(size_t)NH*BN_*DIM];
__device__ __align__(16) __half g_v[(size_t)NH*BN_*DIM];

// ---- PTX helpers ----
__device__ __forceinline__ void cp16(uint32_t saddr, const void* gptr) {
    asm volatile("cp.async.cg.shared.global [%0], [%1], 16;"
                 :: "r"(saddr), "l"(gptr));
}
#define CP_COMMIT() asm volatile("cp.async.commit_group;" ::: "memory")
#define CP_WAIT1()  asm volatile("cp.async.wait_group 1;" ::: "memory")
#define CP_WAIT0()  asm volatile("cp.async.wait_group 0;" ::: "memory")

__device__ __forceinline__ void ldsm_x4(uint32_t& r0, uint32_t& r1,
                                        uint32_t& r2, uint32_t& r3, uint32_t a) {
    asm volatile("ldmatrix.sync.aligned.m8n8.x4.shared.b16 {%0,%1,%2,%3}, [%4];"
                 : "=r"(r0), "=r"(r1), "=r"(r2), "=r"(r3) : "r"(a));
}
__device__ __forceinline__ void ldsm_x4t(uint32_t& r0, uint32_t& r1,
                                         uint32_t& r2, uint32_t& r3, uint32_t a) {
    asm volatile("ldmatrix.sync.aligned.m8n8.x4.trans.shared.b16 {%0,%1,%2,%3}, [%4];"
                 : "=r"(r0), "=r"(r1), "=r"(r2), "=r"(r3) : "r"(a));
}
__device__ __forceinline__ void mma16816(float* c, const uint32_t* a,
                                         uint32_t b0, uint32_t b1) {
    asm volatile("mma.sync.aligned.m16n8k16.row.col.f32.f16.f16.f32 "
                 "{%0,%1,%2,%3}, {%4,%5,%6,%7}, {%8,%9}, {%0,%1,%2,%3};"
                 : "+f"(c[0]), "+f"(c[1]), "+f"(c[2]), "+f"(c[3])
                 : "r"(a[0]), "r"(a[1]), "r"(a[2]), "r"(a[3]), "r"(b0), "r"(b1));
}
__device__ __forceinline__ float ex2f(float x) {
    float y;
    asm("ex2.approx.ftz.f32 %0, %1;" : "=f"(y) : "f"(x));
    return y;
}

// ============================================================
// K1: blocks [0, ADJ_GRID): adjsumh = fp16(sum_w adj).
//   Loads: 8 float4/thread STRIDED by 256 (each LDG lane-contiguous, nL=4;
//   MLP=8). Stores: smem-staged so each thread emits one contiguous 16B STG.
//   blocks [ADJ_GRID, +BIAS_GRID): out = bias broadcast (pre-init for atomics)
// ============================================================
__global__ void adjsum_kernel(const float4* __restrict__ adj,
                              const float4* __restrict__ bout4,
                              float4* __restrict__ out4) {
    __shared__ __align__(16) __half sh[2048];
    const int tid = threadIdx.x;
    if (blockIdx.x < ADJ_GRID) {
        const size_t blk = (size_t)blockIdx.x * 2048;
        float4 t[8];
        #pragma unroll
        for (int j = 0; j < 8; j++) t[j] = adj[blk + j*256 + tid];
        #pragma unroll
        for (int j = 0; j < 8; j++)
            sh[j*256 + tid] = __float2half_rn((t[j].x + t[j].y) + (t[j].z + t[j].w));
        __syncthreads();
        *(uint4*)&g_adjsumh[blk + tid*8] = *(const uint4*)&sh[tid*8];
    } else {
        size_t j = (size_t)(blockIdx.x - ADJ_GRID) * 256 + tid;
        out4[j] = bout4[j & 63];
    }
}

// ============================================================
// K2: q/k/v[h] = fp16( X @ W[h] + b[h] )   (unchanged, proven)
// ============================================================
__global__ void qkv_kernel(const float* __restrict__ X,
                           const float* __restrict__ Wq, const float* __restrict__ bq,
                           const float* __restrict__ Wk, const float* __restrict__ bk,
                           const float* __restrict__ Wv, const float* __restrict__ bv) {
    __shared__ __align__(16) char smem_raw[17408 + TB];
    __half* sA = (__half*)smem_raw;
    __half* sB = (__half*)(smem_raw + 17408);
    float*  sO = (float*)(smem_raw + 17408);
    const int tid  = threadIdx.x;
    const int warp = tid >> 5;
    const int wr = warp >> 2, wc = warp & 3;
    const int row0 = blockIdx.x * 64;
    const int z = blockIdx.y;
    const int mat = z >> 3, h = z & 7;

    const float* Wm = (mat == 0 ? Wq : (mat == 1 ? Wk : Wv)) + (size_t)h*DIM*DIM;
    const float* bm = (mat == 0 ? bq : (mat == 1 ? bk : bv)) + (size_t)h*DIM;
    __half* outp = (mat == 0 ? g_q : (mat == 1 ? g_k : g_v)) + (size_t)h*BN_*DIM;

    for (int idx = tid; idx < 64*32; idx += 256) {
        int r = idx >> 5, c = idx & 31;
        float4 t = *(const float4*)(X + (size_t)(row0 + r)*DIM + c*4);
        __half2* d = (__half2*)(sA + r*LDH + c*4);
        d[0] = __floats2half2_rn(t.x, t.y);
        d[1] = __floats2half2_rn(t.z, t.w);
    }
    for (int idx = tid; idx < 128*32; idx += 256) {
        int r = idx >> 5, c = idx & 31;
        float4 t = *(const float4*)(Wm + (size_t)r*DIM + c*4);
        __half2* d = (__half2*)(sB + r*LDH + c*4);
        d[0] = __floats2half2_rn(t.x, t.y);
        d[1] = __floats2half2_rn(t.z, t.w);
    }
    __syncthreads();

    wmma::fragment<wmma::accumulator,16,16,16,float> acc[2][2];
    #pragma unroll
    for (int i = 0; i < 2; i++)
        #pragma unroll
        for (int j = 0; j < 2; j++) wmma::fill_fragment(acc[i][j], 0.0f);

    #pragma unroll
    for (int k = 0; k < 8; k++) {
        wmma::fragment<wmma::matrix_a,16,16,16,__half,wmma::row_major> fa[2];
        wmma::fragment<wmma::matrix_b,16,16,16,__half,wmma::row_major> fb[2];
        #pragma unroll
        for (int i = 0; i < 2; i++)
            wmma::load_matrix_sync(fa[i], sA + (wr*32 + i*16)*LDH + k*16, LDH);
        #pragma unroll
        for (int j = 0; j < 2; j++)
            wmma::load_matrix_sync(fb[j], sB + (k*16)*LDH + wc*32 + j*16, LDH);
        #pragma unroll
        for (int i = 0; i < 2; i++)
            #pragma unroll
            for (int j = 0; j < 2; j++)
                wmma::mma_sync(acc[i][j], fa[i], fb[j], acc[i][j]);
    }
    __syncthreads();
    #pragma unroll
    for (int i = 0; i < 2; i++)
        #pragma unroll
        for (int j = 0; j < 2; j++)
            wmma::store_matrix_sync(sO + (wr*32 + i*16)*LDS4 + wc*32 + j*16,
                                    acc[i][j], LDS4, wmma::mem_row_major);
    __syncthreads();
    for (int idx = tid; idx < 64*128; idx += 256) {
        int r = idx >> 7, e = idx & 127;
        outp[(size_t)(row0 + r)*DIM + e] = __float2half_rn(sO[r*LDS4 + e] + bm[e]);
    }
}

// ============================================================
// K3 (FUSED FA2 + output projection epilogue — unchanged, proven)
// ============================================================
__global__ __launch_bounds__(256, 1) void fused_attn_fa2(
        const float* __restrict__ Wout, float* __restrict__ out) {
    extern __shared__ __align__(16) char dsm[];
    const uint32_t uBase = (uint32_t)__cvta_generic_to_shared(dsm);

    const int tid  = threadIdx.x;
    const int warp = tid >> 5;
    const int lane = tid & 31;
    const int g    = lane >> 2;
    const int tg   = lane & 3;
    const int n0 = blockIdx.x * 128;
    const int b = blockIdx.y >> 3, h = blockIdx.y & 7;

    const __half* qp  = g_q + (size_t)h*BN_*DIM + (size_t)b*NTOK*DIM;
    const __half* kp  = g_k + (size_t)h*BN_*DIM + (size_t)b*NTOK*DIM;
    const __half* vp  = g_v + (size_t)h*BN_*DIM + (size_t)b*NTOK*DIM;
    const __half* adjp = g_adjsumh + (size_t)b*NTOK*NTOK + (size_t)n0*NTOK;

    const int lrow_a = ((lane >> 3) & 1)*8 + (lane & 7);
    const int lcol_a = (lane >> 4)*8;
    const int lrow_b = ((lane >> 4) & 1)*8 + (lane & 7);
    const int lcol_b = ((lane >> 3) & 1)*8;

    // ---- prologue: stage Q through smem, extract a-frags ----
    for (int idx = tid; idx < 128*16; idx += 256) {
        int r = idx >> 4, c = idx & 15;
        *(uint4*)(dsm + r*272 + c*16) = *(const uint4*)(qp + (size_t)(n0 + r)*DIM + c*8);
    }
    __syncthreads();
    uint32_t aQ[8][4];
    #pragma unroll
    for (int kk = 0; kk < 8; kk++) {
        uint32_t a = uBase + (uint32_t)(warp*16 + lrow_a)*272 + (kk*16 + lcol_a)*2;
        ldsm_x4(aQ[kk][0], aQ[kk][1], aQ[kk][2], aQ[kk][3], a);
    }
    __syncthreads();

    #pragma unroll
    for (int j = 0; j < 2; j++) {
        const uint32_t uK = uBase + j*TB, uV = uBase + (2 + j)*TB, uA = uBase + (4 + j)*TB;
        const int m0 = j*128;
        for (int idx = tid; idx < 128*16; idx += 256) {
            int r = idx >> 4, c = idx & 15;
            cp16(uK + r*272 + c*16, kp + (size_t)(m0 + r)*DIM + c*8);
        }
        for (int idx = tid; idx < 128*16; idx += 256) {
            int r = idx >> 4, c = idx & 15;
            cp16(uV + r*272 + c*16, vp + (size_t)(m0 + r)*DIM + c*8);
        }
        for (int idx = tid; idx < 128*16; idx += 256) {
            int r = idx >> 4, c = idx & 15;
            cp16(uA + r*272 + c*16, adjp + (size_t)r*NTOK + m0 + c*8);
        }
        CP_COMMIT();
    }

    float oacc[16][4];
    #pragma unroll
    for (int j = 0; j < 16; j++)
        #pragma unroll
        for (int e = 0; e < 4; e++) oacc[j][e] = 0.f;
    float lsum0 = 0.f, lsum1 = 0.f;

    for (int it = 0; it < 16; it++) {
        const int bi = it & 1;
        const uint32_t uK = uBase + bi*TB;
        const uint32_t uV = uBase + (2 + bi)*TB;
        const __half* sAdj = (const __half*)(dsm + (size_t)(4 + bi)*TB);

        if (it < 15) { CP_WAIT1(); } else { CP_WAIT0(); }
        __syncthreads();

        // ---- S = Q K^T ----
        float sacc[16][4];
        #pragma unroll
        for (int j = 0; j < 16; j++)
            #pragma unroll
            for (int e = 0; e < 4; e++) sacc[j][e] = 0.f;
        #pragma unroll
        for (int kk = 0; kk < 8; kk++) {
            #pragma unroll
            for (int jjp = 0; jjp < 8; jjp++) {
                uint32_t r0, r1, r2, r3;
                ldsm_x4(r0, r1, r2, r3,
                        uK + (uint32_t)(jjp*16 + lrow_b)*272 + (kk*16 + lcol_b)*2);
                mma16816(sacc[2*jjp],     aQ[kk], r0, r1);
                mma16816(sacc[2*jjp + 1], aQ[kk], r2, r3);
            }
        }

        // ---- exp in registers (ex2 with folded scale) ----
        uint32_t aP[8][4];
        const int row0 = warp*16 + g;
        #pragma unroll
        for (int jj = 0; jj < 16; jj++) {
            const int col = jj*8 + tg*2;
            float2 a0 = __half22float2(*(const __half2*)(sAdj + row0*LDH + col));
            float2 a1 = __half22float2(*(const __half2*)(sAdj + (row0 + 8)*LDH + col));
            float e00 = ex2f(sacc[jj][0] * SC2E * a0.x);
            float e01 = ex2f(sacc[jj][1] * SC2E * a0.y);
            float e10 = ex2f(sacc[jj][2] * SC2E * a1.x);
            float e11 = ex2f(sacc[jj][3] * SC2E * a1.y);
            lsum0 += e00 + e01;
            lsum1 += e10 + e11;
            __half2 p0 = __floats2half2_rn(e00, e01);
            __half2 p1 = __floats2half2_rn(e10, e11);
            aP[jj >> 1][(jj & 1)*2 + 0] = *(uint32_t*)&p0;
            aP[jj >> 1][(jj & 1)*2 + 1] = *(uint32_t*)&p1;
        }

        // ---- O += P @ V ----
        #pragma unroll
        for (int kk = 0; kk < 8; kk++) {
            #pragma unroll
            for (int jop = 0; jop < 8; jop++) {
                uint32_t r0, r1, r2, r3;
                ldsm_x4t(r0, r1, r2, r3,
                         uV + (uint32_t)(kk*16 + lrow_a)*272 + (jop*16 + lcol_a)*2);
                mma16816(oacc[2*jop],     aP[kk], r0, r1);
                mma16816(oacc[2*jop + 1], aP[kk], r2, r3);
            }
        }
        __syncthreads();

        if (it + 2 < 16) {
            const int m2 = (it + 2)*128;
            for (int idx = tid; idx < 128*16; idx += 256) {
                int r = idx >> 4, c = idx & 15;
                cp16(uK + r*272 + c*16, kp + (size_t)(m2 + r)*DIM + c*8);
            }
            for (int idx = tid; idx < 128*16; idx += 256) {
                int r = idx >> 4, c = idx & 15;
                cp16(uV + r*272 + c*16, vp + (size_t)(m2 + r)*DIM + c*8);
            }
            const uint32_t uA = uBase + (4 + bi)*TB;
            for (int idx = tid; idx < 128*16; idx += 256) {
                int r = idx >> 4, c = idx & 15;
                cp16(uA + r*272 + c*16, adjp + (size_t)r*NTOK + m2 + c*8);
            }
            CP_COMMIT();
        }
    }

    // ---- epilogue 1: row sums -> normalized O as A-frags (c->a identity) ----
    lsum0 += __shfl_xor_sync(0xFFFFFFFF, lsum0, 1);
    lsum0 += __shfl_xor_sync(0xFFFFFFFF, lsum0, 2);
    lsum1 += __shfl_xor_sync(0xFFFFFFFF, lsum1, 1);
    lsum1 += __shfl_xor_sync(0xFFFFFFFF, lsum1, 2);
    const float inv0 = 1.0f / lsum0;
    const float inv1 = 1.0f / lsum1;
    uint32_t aO[8][4];
    #pragma unroll
    for (int kk = 0; kk < 8; kk++) {
        __half2 p;
        p = __floats2half2_rn(oacc[2*kk][0]*inv0,   oacc[2*kk][1]*inv0);
        aO[kk][0] = *(uint32_t*)&p;
        p = __floats2half2_rn(oacc[2*kk][2]*inv1,   oacc[2*kk][3]*inv1);
        aO[kk][1] = *(uint32_t*)&p;
        p = __floats2half2_rn(oacc[2*kk+1][0]*inv0, oacc[2*kk+1][1]*inv0);
        aO[kk][2] = *(uint32_t*)&p;
        p = __floats2half2_rn(oacc[2*kk+1][2]*inv1, oacc[2*kk+1][3]*inv1);
        aO[kk][3] = *(uint32_t*)&p;
    }

    // ---- epilogue 2: stage Wout slice [h*128 .. +128) x 256 as fp16 ----
    const float* wsl = Wout + (size_t)(h*DIM)*DOUT;
    for (int idx = tid; idx < 128*64; idx += 256) {
        int r = idx >> 6, c4 = idx & 63;
        float4 t = *(const float4*)(wsl + (size_t)r*DOUT + c4*4);
        __half2* d = (__half2*)((__half*)dsm + r*LDW + c4*4);
        d[0] = __floats2half2_rn(t.x, t.y);
        d[1] = __floats2half2_rn(t.z, t.w);
    }
    __syncthreads();

    // ---- epilogue 3: out_tile(16x256) = O_norm(16x128) @ Wout_slice ----
    float outacc[32][4];
    #pragma unroll
    for (int j = 0; j < 32; j++)
        #pragma unroll
        for (int e = 0; e < 4; e++) outacc[j][e] = 0.f;
    #pragma unroll
    for (int kk = 0; kk < 8; kk++) {
        #pragma unroll
        for (int jop = 0; jop < 16; jop++) {
            uint32_t r0, r1, r2, r3;
            ldsm_x4t(r0, r1, r2, r3,
                     uBase + (uint32_t)(kk*16 + lrow_a)*(LDW*2) + (jop*16 + lcol_a)*2);
            mma16816(outacc[2*jop],     aO[kk], r0, r1);
            mma16816(outacc[2*jop + 1], aO[kk], r2, r3);
        }
    }

    // ---- epilogue 4: atomicAdd into pre-biased out ----
    const int orow = b*NTOK + n0 + warp*16 + g;
    float* o0 = out + (size_t)orow*DOUT;
    float* o1 = o0 + 8*DOUT;
    #pragma unroll
    for (int jt = 0; jt < 32; jt++) {
        const int col = jt*8 + tg*2;
        atomicAdd(o0 + col,     outacc[jt][0]);
        atomicAdd(o0 + col + 1, outacc[jt][1]);
        atomicAdd(o1 + col,     outacc[jt][2]);
        atomicAdd(o1 + col + 1, outacc[jt][3]);
    }
}

// ============================================================
extern "C" void kernel_launch(void* const* d_in, const int* in_sizes, int n_in,
                              void* d_out, int out_size) {
    const float* X    = (const float*)d_in[0];
    const float* adj  = (const float*)d_in[1];
    const float* Wq   = (const float*)d_in[2];
    const float* bq   = (const float*)d_in[3];
    const float* Wk   = (const float*)d_in[4];
    const float* bk   = (const float*)d_in[5];
    const float* Wv   = (const float*)d_in[6];
    const float* bv   = (const float*)d_in[7];
    const float* Wout = (const float*)d_in[8];
    const float* bout = (const float*)d_in[9];
    float* out = (float*)d_out;

    const int fused_smem = 6*TB;   // 208,896 B (epilogue reuse: 67,584 B for Wout)
    cudaFuncSetAttribute(fused_attn_fa2,
                         cudaFuncAttributeMaxDynamicSharedMemorySize, fused_smem);

    adjsum_kernel<<<ADJ_GRID + BIAS_GRID, 256>>>((const float4*)adj,
                                                 (const float4*)bout, (float4*)out);
    qkv_kernel<<<dim3(BN_/64, 3*NH), 256>>>(X, Wq, bq, Wk, bk, Wv, bv);
    fused_attn_fa2<<<dim3(NTOK/128, BB*NH), 256, fused_smem>>>(Wout, out);
}